// round 8
// baseline (speedup 1.0000x reference)
#include <cuda_runtime.h>
#include <cuda_bf16.h>
#include <cstdint>

#define NN 50000
#define EE 500000
#define DD 256
#define HH 4
#define MAXDEG 96
#define REGD 16

// ------------------- device scratch (no allocations allowed) -------------------
// Column layouts PERMUTED: within each 128-col section, col = lane*4 + h.
__device__ float g_WcatT[384 * 256];    // [n=384][k=256], tf32-rounded. rows: 0-127 v | 128-255 A_src | 256-383 A_tgt
__device__ float g_WfT[256 * 128];      // [n=256][k=128], tf32-rounded, k permuted to match g_agg
__device__ float g_big[NN * 384];       // [N, 384] fp32, permuted sections
__device__ float g_Apos[129 * 128];     // [pos][lane*4+h] fp32
__device__ float g_Bdr[64 * 4];
__device__ float g_Bda[8 * 4];
__device__ float g_agg[NN * 128];       // [n][lane*4+h], tf32-rounded (GEMM2 A operand)
__device__ int   g_cnt[NN];
__device__ int   g_slot[NN * MAXDEG];

// ------------------- helpers -------------------
__device__ __forceinline__ unsigned f2tf(float x) {
    unsigned r;
    asm("cvt.rna.tf32.f32 %0, %1;" : "=r"(r) : "f"(x));
    return r;
}
__device__ __forceinline__ float f2tff(float x) { return __uint_as_float(f2tf(x)); }

__device__ __forceinline__ void cp_async16(void* smem, const void* gmem, bool pred) {
    unsigned sa = (unsigned)__cvta_generic_to_shared(smem);
    int sz = pred ? 16 : 0;
    asm volatile("cp.async.cg.shared.global [%0], [%1], 16, %2;" :: "r"(sa), "l"(gmem), "r"(sz));
}
__device__ __forceinline__ void cp_commit() { asm volatile("cp.async.commit_group;"); }
__device__ __forceinline__ void cp_wait0() { asm volatile("cp.async.wait_group 0;" ::: "memory"); }

__device__ __forceinline__ void mma_tf32(float* c, const unsigned* a, const unsigned* b) {
    asm volatile(
        "mma.sync.aligned.m16n8k8.row.col.f32.tf32.tf32.f32 "
        "{%0,%1,%2,%3}, {%4,%5,%6,%7}, {%8,%9}, {%0,%1,%2,%3};"
        : "+f"(c[0]), "+f"(c[1]), "+f"(c[2]), "+f"(c[3])
        : "r"(a[0]), "r"(a[1]), "r"(a[2]), "r"(a[3]), "r"(b[0]), "r"(b[1]));
}

__device__ __forceinline__ float warpsum(float v) {
    #pragma unroll
    for (int o = 16; o > 0; o >>= 1) v += __shfl_xor_sync(0xffffffffu, v, o);
    return v;
}

// ------------------- merged prep kernel (zero cnt + weights + tables) -------------------
__global__ void prep_all_kernel(const float* __restrict__ Wkq,
                                const float* __restrict__ Wv,
                                const float* __restrict__ att_w,
                                const float* __restrict__ Wf,
                                const float* __restrict__ E_pos,
                                const float* __restrict__ E_deprel,
                                const float* __restrict__ E_deparc,
                                const float* __restrict__ edge_w) {
    int t = blockIdx.x * blockDim.x + threadIdx.x;
    if (t < NN) g_cnt[t] = 0;

    if (t < 384 * 256) {
        int c = t >> 8, d = t & 255;
        int sec = c >> 7;
        int m = c & 127;
        int lane = m >> 2, h = m & 3;
        float o;
        if (sec == 0) {
            o = Wv[d * 128 + h * 32 + lane];
        } else {
            int joff = (sec == 2) ? 32 : 0;
            float s = 0.f;
            #pragma unroll
            for (int j = 0; j < 32; j++)
                s += Wkq[d * 128 + h * 32 + j] * att_w[h * 3072 + (joff + j) * 32 + lane];
            o = s;
        }
        g_WcatT[c * 256 + d] = f2tff(o);
        return;
    }
    int u = t - 384 * 256;
    if (u < 256 * 128) {
        int c = u & 127, n = u >> 7;
        int k_orig = (c & 3) * 32 + (c >> 2);
        g_WfT[n * 128 + c] = f2tff(Wf[k_orig * 256 + n]);
        return;
    }
    u -= 256 * 128;
    if (u < 129 * 128) {
        int p = u >> 7, m = u & 127;
        int lane = m >> 2, h = m & 3;
        float s = 0.f;
        #pragma unroll
        for (int j = 0; j < 32; j++)
            s += E_pos[p * 32 + j] * att_w[h * 3072 + (64 + j) * 32 + lane];
        g_Apos[u] = s;
        return;
    }
    u -= 129 * 128;
    if (u < 256) {
        int r = u / 4, h = u % 4;
        float s = 0.f;
        #pragma unroll
        for (int j = 0; j < 32; j++)
            s += E_deprel[r * 32 + j] * edge_w[h * 96 + j];
        g_Bdr[u] = s;
        return;
    }
    u -= 256;
    if (u < 32) {
        int a = u / 4, h = u % 4;
        float s = 0.f;
        #pragma unroll
        for (int j = 0; j < 32; j++)
            s += E_deparc[a * 32 + j] * edge_w[h * 96 + 32 + j];
        g_Bda[u] = s;
    }
}

__global__ void scatter_kernel(const int* __restrict__ edge_index) {
    int e = blockIdx.x * blockDim.x + threadIdx.x;
    if (e >= EE) return;
    int t = edge_index[EE + e];
    int r = atomicAdd(&g_cnt[t], 1);
    if (r < MAXDEG) g_slot[t * MAXDEG + r] = e;
}

// ------------------- tf32 mma.sync GEMM, cp.async double-buffered (round-3 proven) -------------------
template<bool ACVT>
__device__ __forceinline__ void gemm_body(int M, int K,
                                          const float* __restrict__ A, int lda,
                                          const float* __restrict__ BT, int ldbt,
                                          float* __restrict__ C, int ldc,
                                          const float* __restrict__ bias,
                                          float (*As)[128 * 32], float (*Bs)[64 * 32]) {
    int m0 = blockIdx.y * 128;
    int n0 = blockIdx.x * 64;
    int tid = threadIdx.x;
    int wid = tid >> 5, lane = tid & 31;
    int wm = (wid & 3) * 32;
    int wn = (wid >> 2) * 32;
    int r = lane >> 2, cq = lane & 3;

    float acc[2][4][4];
    #pragma unroll
    for (int i = 0; i < 2; i++)
        #pragma unroll
        for (int j = 0; j < 4; j++)
            #pragma unroll
            for (int q = 0; q < 4; q++) acc[i][j][q] = 0.f;

    auto stage = [&](int buf, int k0) {
        #pragma unroll
        for (int l = 0; l < 4; l++) {
            int idx = tid + l * 256;
            int row = idx >> 3, c = idx & 7;
            float* dst = As[buf] + row * 32 + ((c ^ (row & 7)) << 2);
            cp_async16(dst, A + (size_t)(m0 + row) * lda + k0 + c * 4, m0 + row < M);
        }
        #pragma unroll
        for (int l = 0; l < 2; l++) {
            int idx = tid + l * 256;
            int row = idx >> 3, c = idx & 7;
            float* dst = Bs[buf] + row * 32 + ((c ^ (row & 7)) << 2);
            cp_async16(dst, BT + (size_t)(n0 + row) * ldbt + k0 + c * 4, true);
        }
    };

    int T = K >> 5;
    stage(0, 0);
    cp_commit();

    for (int t = 0; t < T; t++) {
        cp_wait0();
        __syncthreads();
        if (t + 1 < T) { stage((t + 1) & 1, (t + 1) * 32); cp_commit(); }

        const float* Ab = As[t & 1];
        const float* Bb = Bs[t & 1];
        #pragma unroll
        for (int kf = 0; kf < 4; kf++) {
            int o0 = (((2 * kf) ^ r) << 2) + cq;
            int o1 = (((2 * kf + 1) ^ r) << 2) + cq;
            unsigned afr[2][4], bfr[4][2];
            #pragma unroll
            for (int mf = 0; mf < 2; mf++) {
                const float* b0 = Ab + (wm + mf * 16 + r) * 32;
                const float* b8 = b0 + 8 * 32;
                if (ACVT) {
                    afr[mf][0] = f2tf(b0[o0]); afr[mf][1] = f2tf(b8[o0]);
                    afr[mf][2] = f2tf(b0[o1]); afr[mf][3] = f2tf(b8[o1]);
                } else {
                    afr[mf][0] = __float_as_uint(b0[o0]); afr[mf][1] = __float_as_uint(b8[o0]);
                    afr[mf][2] = __float_as_uint(b0[o1]); afr[mf][3] = __float_as_uint(b8[o1]);
                }
            }
            #pragma unroll
            for (int nf = 0; nf < 4; nf++) {
                const float* bb = Bb + (wn + nf * 8 + r) * 32;
                bfr[nf][0] = __float_as_uint(bb[o0]);
                bfr[nf][1] = __float_as_uint(bb[o1]);
            }
            #pragma unroll
            for (int mf = 0; mf < 2; mf++)
                #pragma unroll
                for (int nf = 0; nf < 4; nf++)
                    mma_tf32(acc[mf][nf], afr[mf], bfr[nf]);
        }
        __syncthreads();
    }

    #pragma unroll
    for (int mf = 0; mf < 2; mf++) {
        #pragma unroll
        for (int nf = 0; nf < 4; nf++) {
            int col = n0 + wn + nf * 8 + cq * 2;
            float b0 = 0.f, b1 = 0.f;
            if (bias) { b0 = bias[col]; b1 = bias[col + 1]; }
            int row0 = m0 + wm + mf * 16 + r;
            if (row0 < M)
                *(float2*)(C + (size_t)row0 * ldc + col) =
                    make_float2(acc[mf][nf][0] + b0, acc[mf][nf][1] + b1);
            int row1 = row0 + 8;
            if (row1 < M)
                *(float2*)(C + (size_t)row1 * ldc + col) =
                    make_float2(acc[mf][nf][2] + b0, acc[mf][nf][3] + b1);
        }
    }
}

__global__ void gemm1_kernel(const float* __restrict__ inp) {
    __shared__ float As[2][128 * 32];
    __shared__ float Bs[2][64 * 32];
    gemm_body<true>(NN, 256, inp, 256, g_WcatT, 256, g_big, 384, nullptr, As, Bs);
}

__global__ void gemm2_kernel(const float* __restrict__ bias, float* __restrict__ out) {
    __shared__ float As[2][128 * 32];
    __shared__ float Bs[2][64 * 32];
    gemm_body<false>(NN, 128, g_agg, 128, g_WfT, 128, out, 256, bias, As, Bs);
}

// ------------------- edge/attention kernel: one warp per target node -------------------
// Registerized path for d<=16 (covers ~95% of edges): exp scores computed once,
// kept in registers across both passes -> pass 2 gathers only vv.
__global__ void edge_kernel(const int* __restrict__ edge_index,
                            const int* __restrict__ relpos,
                            const int* __restrict__ deprel,
                            const int* __restrict__ deparc,
                            const float* __restrict__ edge_w,
                            float* __restrict__ attn) {
    int warp = (blockIdx.x * blockDim.x + threadIdx.x) >> 5;
    int lane = threadIdx.x & 31;
    if (warp >= NN) return;
    int n = warp;
    const int* src = edge_index;

    float4 at4 = *(const float4*)(g_big + (size_t)n * 384 + 256 + lane * 4);
    float ewn[4], den[4], acc[4];
    #pragma unroll
    for (int h = 0; h < 4; h++) {
        ewn[h] = edge_w[h * 96 + 64 + lane];
        den[h] = 0.f;
        acc[h] = 0.f;
    }

    int d = g_cnt[n];
    if (d > MAXDEG) d = MAXDEG;
    const int* sl = g_slot + n * MAXDEG;
    int se0 = sl[lane], se1 = sl[lane + 32], se2 = sl[lane + 64];
    auto get_e = [&](int i) {
        int v = (i < 32) ? se0 : ((i < 64) ? se1 : se2);
        return __shfl_sync(0xffffffffu, v, i & 31);
    };

    if (d <= REGD) {
        // ---------- registerized path ----------
        float ex0[REGD], ex1[REGD], ex2[REGD], ex3[REGD];
        #pragma unroll
        for (int i = 0; i < REGD; i++) {
            if (i < d) {
                int e = __shfl_sync(0xffffffffu, se0, i);
                int s = src[e];
                int p = relpos[e] + 64;
                float4 as4 = *(const float4*)(g_big + (size_t)s * 384 + 128 + lane * 4);
                float4 ap4 = *(const float4*)(g_Apos + p * 128 + lane * 4);
                float x0 = as4.x + at4.x + ap4.x; x0 = (x0 >= 0.f) ? x0 : 0.2f * x0;
                float x1 = as4.y + at4.y + ap4.y; x1 = (x1 >= 0.f) ? x1 : 0.2f * x1;
                float x2 = as4.z + at4.z + ap4.z; x2 = (x2 >= 0.f) ? x2 : 0.2f * x2;
                float x3 = as4.w + at4.w + ap4.w; x3 = (x3 >= 0.f) ? x3 : 0.2f * x3;
                ex0[i] = __expf(x0); ex1[i] = __expf(x1);
                ex2[i] = __expf(x2); ex3[i] = __expf(x3);
                den[0] += ex0[i]; den[1] += ex1[i];
                den[2] += ex2[i]; den[3] += ex3[i];
            }
        }
        #pragma unroll
        for (int h = 0; h < 4; h++)
            ewn[h] = ewn[h] / (den[h] + 1e-12f);
        #pragma unroll
        for (int i = 0; i < REGD; i++) {
            if (i < d) {
                int e = __shfl_sync(0xffffffffu, se0, i);
                int s = src[e];
                int dr = deprel[e], da = deparc[e];
                float4 vv4 = *(const float4*)(g_big + (size_t)s * 384 + lane * 4);
                float b0 = warpsum(ex0[i] * ewn[0]);
                float b1 = warpsum(ex1[i] * ewn[1]);
                float b2 = warpsum(ex2[i] * ewn[2]);
                float b3 = warpsum(ex3[i] * ewn[3]);
                float y0 = g_Bdr[dr * 4 + 0] + g_Bda[da * 4 + 0] + b0;
                float y1 = g_Bdr[dr * 4 + 1] + g_Bda[da * 4 + 1] + b1;
                float y2 = g_Bdr[dr * 4 + 2] + g_Bda[da * 4 + 2] + b2;
                float y3 = g_Bdr[dr * 4 + 3] + g_Bda[da * 4 + 3] + b3;
                float es0 = (y0 >= 0.f) ? y0 : 0.2f * y0;
                float es1 = (y1 >= 0.f) ? y1 : 0.2f * y1;
                float es2 = (y2 >= 0.f) ? y2 : 0.2f * y2;
                float es3 = (y3 >= 0.f) ? y3 : 0.2f * y3;
                acc[0] += vv4.x * es0;
                acc[1] += vv4.y * es1;
                acc[2] += vv4.z * es2;
                acc[3] += vv4.w * es3;
                if (lane == 0)
                    *(float4*)(attn + (size_t)e * 4) = make_float4(es0, es1, es2, es3);
            }
        }
    } else {
        // ---------- fallback: two-pass recompute (round-3 proven) ----------
        {
            int e = 0, s = 0, p = 0;
            if (d > 0) { e = get_e(0); s = src[e]; p = relpos[e] + 64; }
            for (int i = 0; i < d; i++) {
                int en = e, sn = s, pn = p;
                if (i + 1 < d) { en = get_e(i + 1); sn = src[en]; pn = relpos[en] + 64; }
                float4 as4 = *(const float4*)(g_big + (size_t)s * 384 + 128 + lane * 4);
                float4 ap4 = *(const float4*)(g_Apos + p * 128 + lane * 4);
                float x0 = as4.x + at4.x + ap4.x; x0 = (x0 >= 0.f) ? x0 : 0.2f * x0;
                float x1 = as4.y + at4.y + ap4.y; x1 = (x1 >= 0.f) ? x1 : 0.2f * x1;
                float x2 = as4.z + at4.z + ap4.z; x2 = (x2 >= 0.f) ? x2 : 0.2f * x2;
                float x3 = as4.w + at4.w + ap4.w; x3 = (x3 >= 0.f) ? x3 : 0.2f * x3;
                den[0] += __expf(x0); den[1] += __expf(x1);
                den[2] += __expf(x2); den[3] += __expf(x3);
                e = en; s = sn; p = pn;
            }
        }
        #pragma unroll
        for (int h = 0; h < 4; h++)
            ewn[h] = ewn[h] / (den[h] + 1e-12f);
        {
            int e = 0, s = 0, p = 0, dr = 0, da = 0;
            if (d > 0) { e = get_e(0); s = src[e]; p = relpos[e] + 64; dr = deprel[e]; da = deparc[e]; }
            for (int i = 0; i < d; i++) {
                int en = e, sn = s, pn = p, drn = dr, dan = da;
                if (i + 1 < d) {
                    en = get_e(i + 1); sn = src[en]; pn = relpos[en] + 64;
                    drn = deprel[en]; dan = deparc[en];
                }
                float4 as4 = *(const float4*)(g_big + (size_t)s * 384 + 128 + lane * 4);
                float4 ap4 = *(const float4*)(g_Apos + p * 128 + lane * 4);
                float4 vv4 = *(const float4*)(g_big + (size_t)s * 384 + lane * 4);
                float x0 = as4.x + at4.x + ap4.x; x0 = (x0 >= 0.f) ? x0 : 0.2f * x0;
                float x1 = as4.y + at4.y + ap4.y; x1 = (x1 >= 0.f) ? x1 : 0.2f * x1;
                float x2 = as4.z + at4.z + ap4.z; x2 = (x2 >= 0.f) ? x2 : 0.2f * x2;
                float x3 = as4.w + at4.w + ap4.w; x3 = (x3 >= 0.f) ? x3 : 0.2f * x3;
                float b0 = warpsum(__expf(x0) * ewn[0]);
                float b1 = warpsum(__expf(x1) * ewn[1]);
                float b2 = warpsum(__expf(x2) * ewn[2]);
                float b3 = warpsum(__expf(x3) * ewn[3]);
                float y0 = g_Bdr[dr * 4 + 0] + g_Bda[da * 4 + 0] + b0;
                float y1 = g_Bdr[dr * 4 + 1] + g_Bda[da * 4 + 1] + b1;
                float y2 = g_Bdr[dr * 4 + 2] + g_Bda[da * 4 + 2] + b2;
                float y3 = g_Bdr[dr * 4 + 3] + g_Bda[da * 4 + 3] + b3;
                float es0 = (y0 >= 0.f) ? y0 : 0.2f * y0;
                float es1 = (y1 >= 0.f) ? y1 : 0.2f * y1;
                float es2 = (y2 >= 0.f) ? y2 : 0.2f * y2;
                float es3 = (y3 >= 0.f) ? y3 : 0.2f * y3;
                acc[0] += vv4.x * es0;
                acc[1] += vv4.y * es1;
                acc[2] += vv4.z * es2;
                acc[3] += vv4.w * es3;
                if (lane == 0)
                    *(float4*)(attn + (size_t)e * 4) = make_float4(es0, es1, es2, es3);
                e = en; s = sn; p = pn; dr = drn; da = dan;
            }
        }
    }

    float4 o = make_float4(f2tff(acc[0]), f2tff(acc[1]), f2tff(acc[2]), f2tff(acc[3]));
    *(float4*)(g_agg + (size_t)n * 128 + lane * 4) = o;
}

// ------------------- launch -------------------
extern "C" void kernel_launch(void* const* d_in, const int* in_sizes, int n_in,
                              void* d_out, int out_size) {
    const float* inp        = (const float*)d_in[0];
    const int*   relpos     = (const int*)d_in[1];
    // d_in[2] word_rel_pos_edge: unused
    // d_in[3] deprel_ext_edge: unused
    const int*   edge_index = (const int*)d_in[4];
    const int*   deprel     = (const int*)d_in[5];
    const int*   deparc     = (const int*)d_in[6];
    const float* Wkq        = (const float*)d_in[7];
    const float* Wv         = (const float*)d_in[8];
    const float* att_w      = (const float*)d_in[9];
    const float* edge_w     = (const float*)d_in[10];
    const float* Wf         = (const float*)d_in[11];
    const float* final_bias = (const float*)d_in[12];
    const float* E_deprel   = (const float*)d_in[13];
    const float* E_deparc   = (const float*)d_in[14];
    const float* E_pos      = (const float*)d_in[15];

    float* out  = (float*)d_out;             // [N, 256]
    float* attn = out + (size_t)NN * DD;     // [E, 4]

    // prep work spans: max(NN, 384*256 + 256*128 + 129*128 + 256 + 32)
    int prep_n = 384 * 256 + 256 * 128 + 129 * 128 + 256 + 32;   // 147872 > NN
    prep_all_kernel<<<(prep_n + 255) / 256, 256>>>(Wkq, Wv, att_w, Wf,
                                                   E_pos, E_deprel, E_deparc, edge_w);
    scatter_kernel<<<(EE + 255) / 256, 256>>>(edge_index);

    int mt = (NN + 127) / 128;   // 391
    {
        dim3 grid(384 / 64, mt);
        gemm1_kernel<<<grid, 256>>>(inp);
    }

    edge_kernel<<<(NN * 32 + 255) / 256, 256>>>(edge_index, relpos, deprel, deparc, edge_w, attn);

    {
        dim3 grid(256 / 64, mt);
        gemm2_kernel<<<grid, 256>>>(final_bias, out);
    }
}

// round 9
// speedup vs baseline: 1.8298x; 1.8298x over previous
#include <cuda_runtime.h>
#include <cuda_bf16.h>
#include <cstdint>

#define NN 50000
#define EE 500000
#define DD 256
#define HH 4
#define MAXDEG 96

// ------------------- device scratch (no allocations allowed) -------------------
// Column layouts PERMUTED: within each 128-col section, col = lane*4 + h.
__device__ float g_WcatT[384 * 256];    // [n=384][k=256], tf32-rounded. rows: 0-127 v | 128-255 A_src | 256-383 A_tgt
__device__ float g_WfT[256 * 128];      // [n=256][k=128], tf32-rounded, k permuted to match g_agg
__device__ float g_big[NN * 384];       // [N, 384] fp32, permuted sections
__device__ float g_Apos[129 * 128];     // [pos][lane*4+h] fp32
__device__ float g_Bdr[64 * 4];         // float4-aligned rows
__device__ float g_Bda[8 * 4];
__device__ float g_ewn[NN * 128];       // [n][lane*4+h]: edge_w_lane/(den+eps), pass1 -> pass2
__device__ float g_agg[NN * 128];       // [n][lane*4+h], tf32-rounded (GEMM2 A operand)
__device__ int   g_cnt[NN];
__device__ int   g_slot[NN * MAXDEG];

// ------------------- helpers -------------------
__device__ __forceinline__ unsigned f2tf(float x) {
    unsigned r;
    asm("cvt.rna.tf32.f32 %0, %1;" : "=r"(r) : "f"(x));
    return r;
}
__device__ __forceinline__ float f2tff(float x) { return __uint_as_float(f2tf(x)); }

__device__ __forceinline__ void cp_async16(void* smem, const void* gmem, bool pred) {
    unsigned sa = (unsigned)__cvta_generic_to_shared(smem);
    int sz = pred ? 16 : 0;
    asm volatile("cp.async.cg.shared.global [%0], [%1], 16, %2;" :: "r"(sa), "l"(gmem), "r"(sz));
}
__device__ __forceinline__ void cp_commit() { asm volatile("cp.async.commit_group;"); }
__device__ __forceinline__ void cp_wait0() { asm volatile("cp.async.wait_group 0;" ::: "memory"); }

__device__ __forceinline__ void mma_tf32(float* c, const unsigned* a, const unsigned* b) {
    asm volatile(
        "mma.sync.aligned.m16n8k8.row.col.f32.tf32.tf32.f32 "
        "{%0,%1,%2,%3}, {%4,%5,%6,%7}, {%8,%9}, {%0,%1,%2,%3};"
        : "+f"(c[0]), "+f"(c[1]), "+f"(c[2]), "+f"(c[3])
        : "r"(a[0]), "r"(a[1]), "r"(a[2]), "r"(a[3]), "r"(b[0]), "r"(b[1]));
}

__device__ __forceinline__ float warpsum(float v) {
    #pragma unroll
    for (int o = 16; o > 0; o >>= 1) v += __shfl_xor_sync(0xffffffffu, v, o);
    return v;
}

// ------------------- merged prep kernel (zero cnt + weights + tables) -------------------
__global__ void prep_all_kernel(const float* __restrict__ Wkq,
                                const float* __restrict__ Wv,
                                const float* __restrict__ att_w,
                                const float* __restrict__ Wf,
                                const float* __restrict__ E_pos,
                                const float* __restrict__ E_deprel,
                                const float* __restrict__ E_deparc,
                                const float* __restrict__ edge_w) {
    int t = blockIdx.x * blockDim.x + threadIdx.x;
    if (t < NN) g_cnt[t] = 0;

    if (t < 384 * 256) {
        int c = t >> 8, d = t & 255;
        int sec = c >> 7;
        int m = c & 127;
        int lane = m >> 2, h = m & 3;
        float o;
        if (sec == 0) {
            o = Wv[d * 128 + h * 32 + lane];
        } else {
            int joff = (sec == 2) ? 32 : 0;
            float s = 0.f;
            #pragma unroll
            for (int j = 0; j < 32; j++)
                s += Wkq[d * 128 + h * 32 + j] * att_w[h * 3072 + (joff + j) * 32 + lane];
            o = s;
        }
        g_WcatT[c * 256 + d] = f2tff(o);
        return;
    }
    int u = t - 384 * 256;
    if (u < 256 * 128) {
        int c = u & 127, n = u >> 7;
        int k_orig = (c & 3) * 32 + (c >> 2);
        g_WfT[n * 128 + c] = f2tff(Wf[k_orig * 256 + n]);
        return;
    }
    u -= 256 * 128;
    if (u < 129 * 128) {
        int p = u >> 7, m = u & 127;
        int lane = m >> 2, h = m & 3;
        float s = 0.f;
        #pragma unroll
        for (int j = 0; j < 32; j++)
            s += E_pos[p * 32 + j] * att_w[h * 3072 + (64 + j) * 32 + lane];
        g_Apos[u] = s;
        return;
    }
    u -= 129 * 128;
    if (u < 256) {
        int r = u / 4, h = u % 4;
        float s = 0.f;
        #pragma unroll
        for (int j = 0; j < 32; j++)
            s += E_deprel[r * 32 + j] * edge_w[h * 96 + j];
        g_Bdr[u] = s;
        return;
    }
    u -= 256;
    if (u < 32) {
        int a = u / 4, h = u % 4;
        float s = 0.f;
        #pragma unroll
        for (int j = 0; j < 32; j++)
            s += E_deparc[a * 32 + j] * edge_w[h * 96 + 32 + j];
        g_Bda[u] = s;
    }
}

__global__ void scatter_kernel(const int* __restrict__ edge_index) {
    int e = blockIdx.x * blockDim.x + threadIdx.x;
    if (e >= EE) return;
    int t = edge_index[EE + e];
    int r = atomicAdd(&g_cnt[t], 1);
    if (r < MAXDEG) g_slot[t * MAXDEG + r] = e;
}

// ------------------- tf32 mma.sync GEMM, cp.async double-buffered (round-3 proven) -------------------
template<bool ACVT>
__device__ __forceinline__ void gemm_body(int M, int K,
                                          const float* __restrict__ A, int lda,
                                          const float* __restrict__ BT, int ldbt,
                                          float* __restrict__ C, int ldc,
                                          const float* __restrict__ bias,
                                          float (*As)[128 * 32], float (*Bs)[64 * 32]) {
    int m0 = blockIdx.y * 128;
    int n0 = blockIdx.x * 64;
    int tid = threadIdx.x;
    int wid = tid >> 5, lane = tid & 31;
    int wm = (wid & 3) * 32;
    int wn = (wid >> 2) * 32;
    int r = lane >> 2, cq = lane & 3;

    float acc[2][4][4];
    #pragma unroll
    for (int i = 0; i < 2; i++)
        #pragma unroll
        for (int j = 0; j < 4; j++)
            #pragma unroll
            for (int q = 0; q < 4; q++) acc[i][j][q] = 0.f;

    auto stage = [&](int buf, int k0) {
        #pragma unroll
        for (int l = 0; l < 4; l++) {
            int idx = tid + l * 256;
            int row = idx >> 3, c = idx & 7;
            float* dst = As[buf] + row * 32 + ((c ^ (row & 7)) << 2);
            cp_async16(dst, A + (size_t)(m0 + row) * lda + k0 + c * 4, m0 + row < M);
        }
        #pragma unroll
        for (int l = 0; l < 2; l++) {
            int idx = tid + l * 256;
            int row = idx >> 3, c = idx & 7;
            float* dst = Bs[buf] + row * 32 + ((c ^ (row & 7)) << 2);
            cp_async16(dst, BT + (size_t)(n0 + row) * ldbt + k0 + c * 4, true);
        }
    };

    int T = K >> 5;
    stage(0, 0);
    cp_commit();

    for (int t = 0; t < T; t++) {
        cp_wait0();
        __syncthreads();
        if (t + 1 < T) { stage((t + 1) & 1, (t + 1) * 32); cp_commit(); }

        const float* Ab = As[t & 1];
        const float* Bb = Bs[t & 1];
        #pragma unroll
        for (int kf = 0; kf < 4; kf++) {
            int o0 = (((2 * kf) ^ r) << 2) + cq;
            int o1 = (((2 * kf + 1) ^ r) << 2) + cq;
            unsigned afr[2][4], bfr[4][2];
            #pragma unroll
            for (int mf = 0; mf < 2; mf++) {
                const float* b0 = Ab + (wm + mf * 16 + r) * 32;
                const float* b8 = b0 + 8 * 32;
                if (ACVT) {
                    afr[mf][0] = f2tf(b0[o0]); afr[mf][1] = f2tf(b8[o0]);
                    afr[mf][2] = f2tf(b0[o1]); afr[mf][3] = f2tf(b8[o1]);
                } else {
                    afr[mf][0] = __float_as_uint(b0[o0]); afr[mf][1] = __float_as_uint(b8[o0]);
                    afr[mf][2] = __float_as_uint(b0[o1]); afr[mf][3] = __float_as_uint(b8[o1]);
                }
            }
            #pragma unroll
            for (int nf = 0; nf < 4; nf++) {
                const float* bb = Bb + (wn + nf * 8 + r) * 32;
                bfr[nf][0] = __float_as_uint(bb[o0]);
                bfr[nf][1] = __float_as_uint(bb[o1]);
            }
            #pragma unroll
            for (int mf = 0; mf < 2; mf++)
                #pragma unroll
                for (int nf = 0; nf < 4; nf++)
                    mma_tf32(acc[mf][nf], afr[mf], bfr[nf]);
        }
        __syncthreads();
    }

    #pragma unroll
    for (int mf = 0; mf < 2; mf++) {
        #pragma unroll
        for (int nf = 0; nf < 4; nf++) {
            int col = n0 + wn + nf * 8 + cq * 2;
            float b0 = 0.f, b1 = 0.f;
            if (bias) { b0 = bias[col]; b1 = bias[col + 1]; }
            int row0 = m0 + wm + mf * 16 + r;
            if (row0 < M)
                *(float2*)(C + (size_t)row0 * ldc + col) =
                    make_float2(acc[mf][nf][0] + b0, acc[mf][nf][1] + b1);
            int row1 = row0 + 8;
            if (row1 < M)
                *(float2*)(C + (size_t)row1 * ldc + col) =
                    make_float2(acc[mf][nf][2] + b0, acc[mf][nf][3] + b1);
        }
    }
}

__global__ void gemm1_kernel(const float* __restrict__ inp) {
    __shared__ float As[2][128 * 32];
    __shared__ float Bs[2][64 * 32];
    gemm_body<true>(NN, 256, inp, 256, g_WcatT, 256, g_big, 384, nullptr, As, Bs);
}

__global__ void gemm2_kernel(const float* __restrict__ bias, float* __restrict__ out) {
    __shared__ float As[2][128 * 32];
    __shared__ float Bs[2][64 * 32];
    gemm_body<false>(NN, 128, g_agg, 128, g_WfT, 128, out, 256, bias, As, Bs);
}

// ------------------- edge pass 1: softmax denominators -> g_ewn -------------------
// Minimal register footprint => high occupancy (this kernel is latency-bound).
__global__ void edge_pass1_kernel(const int* __restrict__ edge_index,
                                  const int* __restrict__ relpos,
                                  const float* __restrict__ edge_w) {
    int warp = (blockIdx.x * blockDim.x + threadIdx.x) >> 5;
    int lane = threadIdx.x & 31;
    if (warp >= NN) return;
    int n = warp;
    const int* src = edge_index;

    float4 at4 = *(const float4*)(g_big + (size_t)n * 384 + 256 + lane * 4);
    float den0 = 0.f, den1 = 0.f, den2 = 0.f, den3 = 0.f;

    int d = g_cnt[n];
    if (d > MAXDEG) d = MAXDEG;
    const int* sl = g_slot + n * MAXDEG;
    int se0 = sl[lane], se1 = sl[lane + 32], se2 = sl[lane + 64];
    auto get_e = [&](int i) {
        int v = (i < 32) ? se0 : ((i < 64) ? se1 : se2);
        return __shfl_sync(0xffffffffu, v, i & 31);
    };

    int e = 0, s = 0, p = 0;
    if (d > 0) { e = get_e(0); s = src[e]; p = relpos[e] + 64; }
    for (int i = 0; i < d; i++) {
        int en = e, sn = s, pn = p;
        if (i + 1 < d) { en = get_e(i + 1); sn = src[en]; pn = relpos[en] + 64; }
        float4 as4 = *(const float4*)(g_big + (size_t)s * 384 + 128 + lane * 4);
        float4 ap4 = *(const float4*)(g_Apos + p * 128 + lane * 4);
        float x0 = as4.x + at4.x + ap4.x; x0 = (x0 >= 0.f) ? x0 : 0.2f * x0;
        float x1 = as4.y + at4.y + ap4.y; x1 = (x1 >= 0.f) ? x1 : 0.2f * x1;
        float x2 = as4.z + at4.z + ap4.z; x2 = (x2 >= 0.f) ? x2 : 0.2f * x2;
        float x3 = as4.w + at4.w + ap4.w; x3 = (x3 >= 0.f) ? x3 : 0.2f * x3;
        den0 += __expf(x0); den1 += __expf(x1);
        den2 += __expf(x2); den3 += __expf(x3);
        e = en; s = sn; p = pn;
    }

    float4 o;
    o.x = edge_w[0 * 96 + 64 + lane] / (den0 + 1e-12f);
    o.y = edge_w[1 * 96 + 64 + lane] / (den1 + 1e-12f);
    o.z = edge_w[2 * 96 + 64 + lane] / (den2 + 1e-12f);
    o.w = edge_w[3 * 96 + 64 + lane] / (den3 + 1e-12f);
    *(float4*)(g_ewn + (size_t)n * 128 + lane * 4) = o;
}

// ------------------- edge pass 2: recompute exp, edge scores, attn, v accumulation -------------------
__global__ void edge_pass2_kernel(const int* __restrict__ edge_index,
                                  const int* __restrict__ relpos,
                                  const int* __restrict__ deprel,
                                  const int* __restrict__ deparc,
                                  float* __restrict__ attn) {
    int warp = (blockIdx.x * blockDim.x + threadIdx.x) >> 5;
    int lane = threadIdx.x & 31;
    if (warp >= NN) return;
    int n = warp;
    const int* src = edge_index;

    float4 at4 = *(const float4*)(g_big + (size_t)n * 384 + 256 + lane * 4);
    float4 ew4 = *(const float4*)(g_ewn + (size_t)n * 128 + lane * 4);
    float acc0 = 0.f, acc1 = 0.f, acc2 = 0.f, acc3 = 0.f;

    int d = g_cnt[n];
    if (d > MAXDEG) d = MAXDEG;
    const int* sl = g_slot + n * MAXDEG;
    int se0 = sl[lane], se1 = sl[lane + 32], se2 = sl[lane + 64];
    auto get_e = [&](int i) {
        int v = (i < 32) ? se0 : ((i < 64) ? se1 : se2);
        return __shfl_sync(0xffffffffu, v, i & 31);
    };

    int e = 0, s = 0, p = 0, dr = 0, da = 0;
    if (d > 0) { e = get_e(0); s = src[e]; p = relpos[e] + 64; dr = deprel[e]; da = deparc[e]; }
    for (int i = 0; i < d; i++) {
        int en = e, sn = s, pn = p, drn = dr, dan = da;
        if (i + 1 < d) {
            en = get_e(i + 1); sn = src[en]; pn = relpos[en] + 64;
            drn = deprel[en]; dan = deparc[en];
        }
        float4 as4 = *(const float4*)(g_big + (size_t)s * 384 + 128 + lane * 4);
        float4 ap4 = *(const float4*)(g_Apos + p * 128 + lane * 4);
        float4 vv4 = *(const float4*)(g_big + (size_t)s * 384 + lane * 4);
        float4 bdr4 = *(const float4*)(g_Bdr + dr * 4);
        float4 bda4 = *(const float4*)(g_Bda + da * 4);
        float x0 = as4.x + at4.x + ap4.x; x0 = (x0 >= 0.f) ? x0 : 0.2f * x0;
        float x1 = as4.y + at4.y + ap4.y; x1 = (x1 >= 0.f) ? x1 : 0.2f * x1;
        float x2 = as4.z + at4.z + ap4.z; x2 = (x2 >= 0.f) ? x2 : 0.2f * x2;
        float x3 = as4.w + at4.w + ap4.w; x3 = (x3 >= 0.f) ? x3 : 0.2f * x3;
        float b0 = warpsum(__expf(x0) * ew4.x);
        float b1 = warpsum(__expf(x1) * ew4.y);
        float b2 = warpsum(__expf(x2) * ew4.z);
        float b3 = warpsum(__expf(x3) * ew4.w);
        float y0 = bdr4.x + bda4.x + b0;
        float y1 = bdr4.y + bda4.y + b1;
        float y2 = bdr4.z + bda4.z + b2;
        float y3 = bdr4.w + bda4.w + b3;
        float es0 = (y0 >= 0.f) ? y0 : 0.2f * y0;
        float es1 = (y1 >= 0.f) ? y1 : 0.2f * y1;
        float es2 = (y2 >= 0.f) ? y2 : 0.2f * y2;
        float es3 = (y3 >= 0.f) ? y3 : 0.2f * y3;
        acc0 += vv4.x * es0;
        acc1 += vv4.y * es1;
        acc2 += vv4.z * es2;
        acc3 += vv4.w * es3;
        if (lane == 0)
            *(float4*)(attn + (size_t)e * 4) = make_float4(es0, es1, es2, es3);
        e = en; s = sn; p = pn; dr = drn; da = dan;
    }

    float4 o = make_float4(f2tff(acc0), f2tff(acc1), f2tff(acc2), f2tff(acc3));
    *(float4*)(g_agg + (size_t)n * 128 + lane * 4) = o;
}

// ------------------- launch -------------------
extern "C" void kernel_launch(void* const* d_in, const int* in_sizes, int n_in,
                              void* d_out, int out_size) {
    const float* inp        = (const float*)d_in[0];
    const int*   relpos     = (const int*)d_in[1];
    // d_in[2] word_rel_pos_edge: unused
    // d_in[3] deprel_ext_edge: unused
    const int*   edge_index = (const int*)d_in[4];
    const int*   deprel     = (const int*)d_in[5];
    const int*   deparc     = (const int*)d_in[6];
    const float* Wkq        = (const float*)d_in[7];
    const float* Wv         = (const float*)d_in[8];
    const float* att_w      = (const float*)d_in[9];
    const float* edge_w     = (const float*)d_in[10];
    const float* Wf         = (const float*)d_in[11];
    const float* final_bias = (const float*)d_in[12];
    const float* E_deprel   = (const float*)d_in[13];
    const float* E_deparc   = (const float*)d_in[14];
    const float* E_pos      = (const float*)d_in[15];

    float* out  = (float*)d_out;             // [N, 256]
    float* attn = out + (size_t)NN * DD;     // [E, 4]

    int prep_n = 384 * 256 + 256 * 128 + 129 * 128 + 256 + 32;   // 147872 > NN
    prep_all_kernel<<<(prep_n + 255) / 256, 256>>>(Wkq, Wv, att_w, Wf,
                                                   E_pos, E_deprel, E_deparc, edge_w);
    scatter_kernel<<<(EE + 255) / 256, 256>>>(edge_index);

    int mt = (NN + 127) / 128;   // 391
    {
        dim3 grid(384 / 64, mt);
        gemm1_kernel<<<grid, 256>>>(inp);
    }

    edge_pass1_kernel<<<(NN * 32 + 255) / 256, 256>>>(edge_index, relpos, edge_w);
    edge_pass2_kernel<<<(NN * 32 + 255) / 256, 256>>>(edge_index, relpos, deprel, deparc, attn);

    {
        dim3 grid(256 / 64, mt);
        gemm2_kernel<<<grid, 256>>>(final_bias, out);
    }
}

// round 10
// speedup vs baseline: 2.1556x; 1.1781x over previous
#include <cuda_runtime.h>
#include <cuda_bf16.h>
#include <cstdint>

#define NN 50000
#define EE 500000
#define DD 256
#define HH 4
#define MAXDEG 96

// ------------------- device scratch (no allocations allowed) -------------------
// 128-col sections in NATURAL order: col = h*32 + k. float4 at lane*4 holds
// (h = lane>>3, k = (lane&7)*4 .. +3).
__device__ float g_WcatT[384 * 256];    // [n=384][k=256], tf32-rounded. rows: 0-127 v | 128-255 A_src | 256-383 A_tgt
__device__ float g_WfT[256 * 128];      // [n=256][k=128], tf32-rounded (no perm needed now)
__device__ float g_big[NN * 384];       // [N, 384] fp32
__device__ float g_Apos[129 * 128];     // [pos][h*32+k] fp32
__device__ float g_Bdr[64 * 4];         // [deprel][h]
__device__ float g_Bda[8 * 4];          // [deparc][h]
__device__ float g_agg[NN * 128];       // [n][h*32+dv], tf32-rounded (GEMM2 A operand)
__device__ int   g_cnt[NN];
__device__ int   g_slot[NN * MAXDEG];

// ------------------- helpers -------------------
__device__ __forceinline__ unsigned f2tf(float x) {
    unsigned r;
    asm("cvt.rna.tf32.f32 %0, %1;" : "=r"(r) : "f"(x));
    return r;
}
__device__ __forceinline__ float f2tff(float x) { return __uint_as_float(f2tf(x)); }

__device__ __forceinline__ void cp_async16(void* smem, const void* gmem, bool pred) {
    unsigned sa = (unsigned)__cvta_generic_to_shared(smem);
    int sz = pred ? 16 : 0;
    asm volatile("cp.async.cg.shared.global [%0], [%1], 16, %2;" :: "r"(sa), "l"(gmem), "r"(sz));
}
__device__ __forceinline__ void cp_commit() { asm volatile("cp.async.commit_group;"); }
__device__ __forceinline__ void cp_wait0() { asm volatile("cp.async.wait_group 0;" ::: "memory"); }

__device__ __forceinline__ void mma_tf32(float* c, const unsigned* a, const unsigned* b) {
    asm volatile(
        "mma.sync.aligned.m16n8k8.row.col.f32.tf32.tf32.f32 "
        "{%0,%1,%2,%3}, {%4,%5,%6,%7}, {%8,%9}, {%0,%1,%2,%3};"
        : "+f"(c[0]), "+f"(c[1]), "+f"(c[2]), "+f"(c[3])
        : "r"(a[0]), "r"(a[1]), "r"(a[2]), "r"(a[3]), "r"(b[0]), "r"(b[1]));
}

// ------------------- merged prep kernel (zero cnt + weights + tables) -------------------
__global__ void prep_all_kernel(const float* __restrict__ Wkq,
                                const float* __restrict__ Wv,
                                const float* __restrict__ att_w,
                                const float* __restrict__ Wf,
                                const float* __restrict__ E_pos,
                                const float* __restrict__ E_deprel,
                                const float* __restrict__ E_deparc,
                                const float* __restrict__ edge_w) {
    int t = blockIdx.x * blockDim.x + threadIdx.x;
    if (t < NN) g_cnt[t] = 0;

    if (t < 384 * 256) {
        int c = t >> 8, d = t & 255;
        int sec = c >> 7;
        int m = c & 127;               // m = h*32 + k (natural)
        int h = m >> 5, k = m & 31;
        float o;
        if (sec == 0) {
            o = Wv[d * 128 + m];
        } else {
            int joff = (sec == 2) ? 32 : 0;
            float s = 0.f;
            #pragma unroll
            for (int j = 0; j < 32; j++)
                s += Wkq[d * 128 + h * 32 + j] * att_w[h * 3072 + (joff + j) * 32 + k];
            o = s;
        }
        g_WcatT[c * 256 + d] = f2tff(o);
        return;
    }
    int u = t - 384 * 256;
    if (u < 256 * 128) {
        int c = u & 127, n = u >> 7;   // g_agg col c = h*32+dv matches Wf row c directly
        g_WfT[n * 128 + c] = f2tff(Wf[c * 256 + n]);
        return;
    }
    u -= 256 * 128;
    if (u < 129 * 128) {
        int p = u >> 7, m = u & 127;
        int h = m >> 5, k = m & 31;
        float s = 0.f;
        #pragma unroll
        for (int j = 0; j < 32; j++)
            s += E_pos[p * 32 + j] * att_w[h * 3072 + (64 + j) * 32 + k];
        g_Apos[u] = s;
        return;
    }
    u -= 129 * 128;
    if (u < 256) {
        int r = u / 4, h = u % 4;
        float s = 0.f;
        #pragma unroll
        for (int j = 0; j < 32; j++)
            s += E_deprel[r * 32 + j] * edge_w[h * 96 + j];
        g_Bdr[u] = s;
        return;
    }
    u -= 256;
    if (u < 32) {
        int a = u / 4, h = u % 4;
        float s = 0.f;
        #pragma unroll
        for (int j = 0; j < 32; j++)
            s += E_deparc[a * 32 + j] * edge_w[h * 96 + 32 + j];
        g_Bda[u] = s;
    }
}

__global__ void scatter_kernel(const int* __restrict__ edge_index) {
    int e = blockIdx.x * blockDim.x + threadIdx.x;
    if (e >= EE) return;
    int t = edge_index[EE + e];
    int r = atomicAdd(&g_cnt[t], 1);
    if (r < MAXDEG) g_slot[t * MAXDEG + r] = e;
}

// ------------------- tf32 mma.sync GEMM, cp.async double-buffered (round-3 proven) -------------------
template<bool ACVT>
__device__ __forceinline__ void gemm_body(int M, int K,
                                          const float* __restrict__ A, int lda,
                                          const float* __restrict__ BT, int ldbt,
                                          float* __restrict__ C, int ldc,
                                          const float* __restrict__ bias,
                                          float (*As)[128 * 32], float (*Bs)[64 * 32]) {
    int m0 = blockIdx.y * 128;
    int n0 = blockIdx.x * 64;
    int tid = threadIdx.x;
    int wid = tid >> 5, lane = tid & 31;
    int wm = (wid & 3) * 32;
    int wn = (wid >> 2) * 32;
    int r = lane >> 2, cq = lane & 3;

    float acc[2][4][4];
    #pragma unroll
    for (int i = 0; i < 2; i++)
        #pragma unroll
        for (int j = 0; j < 4; j++)
            #pragma unroll
            for (int q = 0; q < 4; q++) acc[i][j][q] = 0.f;

    auto stage = [&](int buf, int k0) {
        #pragma unroll
        for (int l = 0; l < 4; l++) {
            int idx = tid + l * 256;
            int row = idx >> 3, c = idx & 7;
            float* dst = As[buf] + row * 32 + ((c ^ (row & 7)) << 2);
            cp_async16(dst, A + (size_t)(m0 + row) * lda + k0 + c * 4, m0 + row < M);
        }
        #pragma unroll
        for (int l = 0; l < 2; l++) {
            int idx = tid + l * 256;
            int row = idx >> 3, c = idx & 7;
            float* dst = Bs[buf] + row * 32 + ((c ^ (row & 7)) << 2);
            cp_async16(dst, BT + (size_t)(n0 + row) * ldbt + k0 + c * 4, true);
        }
    };

    int T = K >> 5;
    stage(0, 0);
    cp_commit();

    for (int t = 0; t < T; t++) {
        cp_wait0();
        __syncthreads();
        if (t + 1 < T) { stage((t + 1) & 1, (t + 1) * 32); cp_commit(); }

        const float* Ab = As[t & 1];
        const float* Bb = Bs[t & 1];
        #pragma unroll
        for (int kf = 0; kf < 4; kf++) {
            int o0 = (((2 * kf) ^ r) << 2) + cq;
            int o1 = (((2 * kf + 1) ^ r) << 2) + cq;
            unsigned afr[2][4], bfr[4][2];
            #pragma unroll
            for (int mf = 0; mf < 2; mf++) {
                const float* b0 = Ab + (wm + mf * 16 + r) * 32;
                const float* b8 = b0 + 8 * 32;
                if (ACVT) {
                    afr[mf][0] = f2tf(b0[o0]); afr[mf][1] = f2tf(b8[o0]);
                    afr[mf][2] = f2tf(b0[o1]); afr[mf][3] = f2tf(b8[o1]);
                } else {
                    afr[mf][0] = __float_as_uint(b0[o0]); afr[mf][1] = __float_as_uint(b8[o0]);
                    afr[mf][2] = __float_as_uint(b0[o1]); afr[mf][3] = __float_as_uint(b8[o1]);
                }
            }
            #pragma unroll
            for (int nf = 0; nf < 4; nf++) {
                const float* bb = Bb + (wn + nf * 8 + r) * 32;
                bfr[nf][0] = __float_as_uint(bb[o0]);
                bfr[nf][1] = __float_as_uint(bb[o1]);
            }
            #pragma unroll
            for (int mf = 0; mf < 2; mf++)
                #pragma unroll
                for (int nf = 0; nf < 4; nf++)
                    mma_tf32(acc[mf][nf], afr[mf], bfr[nf]);
        }
        __syncthreads();
    }

    #pragma unroll
    for (int mf = 0; mf < 2; mf++) {
        #pragma unroll
        for (int nf = 0; nf < 4; nf++) {
            int col = n0 + wn + nf * 8 + cq * 2;
            float b0 = 0.f, b1 = 0.f;
            if (bias) { b0 = bias[col]; b1 = bias[col + 1]; }
            int row0 = m0 + wm + mf * 16 + r;
            if (row0 < M)
                *(float2*)(C + (size_t)row0 * ldc + col) =
                    make_float2(acc[mf][nf][0] + b0, acc[mf][nf][1] + b1);
            int row1 = row0 + 8;
            if (row1 < M)
                *(float2*)(C + (size_t)row1 * ldc + col) =
                    make_float2(acc[mf][nf][2] + b0, acc[mf][nf][3] + b1);
        }
    }
}

__global__ void gemm1_kernel(const float* __restrict__ inp) {
    __shared__ float As[2][128 * 32];
    __shared__ float Bs[2][64 * 32];
    gemm_body<true>(NN, 256, inp, 256, g_WcatT, 256, g_big, 384, nullptr, As, Bs);
}

__global__ void gemm2_kernel(const float* __restrict__ bias, float* __restrict__ out) {
    __shared__ float As[2][128 * 32];
    __shared__ float Bs[2][64 * 32];
    gemm_body<false>(NN, 128, g_agg, 128, g_WfT, 128, out, 256, bias, As, Bs);
}

// ------------------- edge/attention kernel: one warp per target node -------------------
// Natural [h*32+k] layout: lane owns (h = lane>>3, k-quad = (lane&7)*4).
// Denominators are fully per-lane; the beta reduction is an intra-lane 4-dot
// plus a 3-shfl butterfly over the 8 lanes of the head group.
__global__ void edge_kernel(const int* __restrict__ edge_index,
                            const int* __restrict__ relpos,
                            const int* __restrict__ deprel,
                            const int* __restrict__ deparc,
                            const float* __restrict__ edge_w,
                            float* __restrict__ attn) {
    int warp = (blockIdx.x * blockDim.x + threadIdx.x) >> 5;
    int lane = threadIdx.x & 31;
    if (warp >= NN) return;
    int n = warp;
    const int* src = edge_index;
    int h = lane >> 3;
    int kb = (lane & 7) * 4;

    float4 at4 = *(const float4*)(g_big + (size_t)n * 384 + 256 + lane * 4);
    float ew0 = edge_w[h * 96 + 64 + kb + 0];
    float ew1 = edge_w[h * 96 + 64 + kb + 1];
    float ew2 = edge_w[h * 96 + 64 + kb + 2];
    float ew3 = edge_w[h * 96 + 64 + kb + 3];
    float den0 = 0.f, den1 = 0.f, den2 = 0.f, den3 = 0.f;
    float acc0 = 0.f, acc1 = 0.f, acc2 = 0.f, acc3 = 0.f;

    int d = g_cnt[n];
    if (d > MAXDEG) d = MAXDEG;
    const int* sl = g_slot + n * MAXDEG;
    int se0 = sl[lane], se1 = sl[lane + 32], se2 = sl[lane + 64];
    auto get_e = [&](int i) {
        int v = (i < 32) ? se0 : ((i < 64) ? se1 : se2);
        return __shfl_sync(0xffffffffu, v, i & 31);
    };

    // pass 1: denominators (per-lane, no reduction)
    {
        int e = 0, s = 0, p = 0;
        if (d > 0) { e = get_e(0); s = src[e]; p = relpos[e] + 64; }
        for (int i = 0; i < d; i++) {
            int en = e, sn = s, pn = p;
            if (i + 1 < d) { en = get_e(i + 1); sn = src[en]; pn = relpos[en] + 64; }
            float4 as4 = *(const float4*)(g_big + (size_t)s * 384 + 128 + lane * 4);
            float4 ap4 = *(const float4*)(g_Apos + p * 128 + lane * 4);
            float x0 = as4.x + at4.x + ap4.x; x0 = (x0 >= 0.f) ? x0 : 0.2f * x0;
            float x1 = as4.y + at4.y + ap4.y; x1 = (x1 >= 0.f) ? x1 : 0.2f * x1;
            float x2 = as4.z + at4.z + ap4.z; x2 = (x2 >= 0.f) ? x2 : 0.2f * x2;
            float x3 = as4.w + at4.w + ap4.w; x3 = (x3 >= 0.f) ? x3 : 0.2f * x3;
            den0 += __expf(x0); den1 += __expf(x1);
            den2 += __expf(x2); den3 += __expf(x3);
            e = en; s = sn; p = pn;
        }
    }

    // fold 1/(den+eps) into beta weights (per-lane)
    ew0 = ew0 / (den0 + 1e-12f);
    ew1 = ew1 / (den1 + 1e-12f);
    ew2 = ew2 / (den2 + 1e-12f);
    ew3 = ew3 / (den3 + 1e-12f);

    // pass 2: recompute exp, cheap 8-lane reduction, attn, v accumulation
    {
        int e = 0, s = 0, p = 0, dr = 0, da = 0;
        if (d > 0) { e = get_e(0); s = src[e]; p = relpos[e] + 64; dr = deprel[e]; da = deparc[e]; }
        for (int i = 0; i < d; i++) {
            int en = e, sn = s, pn = p, drn = dr, dan = da;
            if (i + 1 < d) {
                en = get_e(i + 1); sn = src[en]; pn = relpos[en] + 64;
                drn = deprel[en]; dan = deparc[en];
            }
            float4 as4 = *(const float4*)(g_big + (size_t)s * 384 + 128 + lane * 4);
            float4 ap4 = *(const float4*)(g_Apos + p * 128 + lane * 4);
            float4 vv4 = *(const float4*)(g_big + (size_t)s * 384 + lane * 4);
            float bdr = g_Bdr[dr * 4 + h];
            float bda = g_Bda[da * 4 + h];
            float x0 = as4.x + at4.x + ap4.x; x0 = (x0 >= 0.f) ? x0 : 0.2f * x0;
            float x1 = as4.y + at4.y + ap4.y; x1 = (x1 >= 0.f) ? x1 : 0.2f * x1;
            float x2 = as4.z + at4.z + ap4.z; x2 = (x2 >= 0.f) ? x2 : 0.2f * x2;
            float x3 = as4.w + at4.w + ap4.w; x3 = (x3 >= 0.f) ? x3 : 0.2f * x3;
            float pl = __expf(x0) * ew0 + __expf(x1) * ew1
                     + __expf(x2) * ew2 + __expf(x3) * ew3;
            pl += __shfl_xor_sync(0xffffffffu, pl, 1);
            pl += __shfl_xor_sync(0xffffffffu, pl, 2);
            pl += __shfl_xor_sync(0xffffffffu, pl, 4);
            float y = bdr + bda + pl;
            float es = (y >= 0.f) ? y : 0.2f * y;
            acc0 += vv4.x * es;
            acc1 += vv4.y * es;
            acc2 += vv4.z * es;
            acc3 += vv4.w * es;
            if ((lane & 7) == 0)
                attn[(size_t)e * 4 + h] = es;     // lanes 0/8/16/24 -> one 16B txn
            e = en; s = sn; p = pn; dr = drn; da = dan;
        }
    }

    float4 o = make_float4(f2tff(acc0), f2tff(acc1), f2tff(acc2), f2tff(acc3));
    *(float4*)(g_agg + (size_t)n * 128 + lane * 4) = o;
}

// ------------------- launch -------------------
extern "C" void kernel_launch(void* const* d_in, const int* in_sizes, int n_in,
                              void* d_out, int out_size) {
    const float* inp        = (const float*)d_in[0];
    const int*   relpos     = (const int*)d_in[1];
    // d_in[2] word_rel_pos_edge: unused
    // d_in[3] deprel_ext_edge: unused
    const int*   edge_index = (const int*)d_in[4];
    const int*   deprel     = (const int*)d_in[5];
    const int*   deparc     = (const int*)d_in[6];
    const float* Wkq        = (const float*)d_in[7];
    const float* Wv         = (const float*)d_in[8];
    const float* att_w      = (const float*)d_in[9];
    const float* edge_w     = (const float*)d_in[10];
    const float* Wf         = (const float*)d_in[11];
    const float* final_bias = (const float*)d_in[12];
    const float* E_deprel   = (const float*)d_in[13];
    const float* E_deparc   = (const float*)d_in[14];
    const float* E_pos      = (const float*)d_in[15];

    float* out  = (float*)d_out;             // [N, 256]
    float* attn = out + (size_t)NN * DD;     // [E, 4]

    int prep_n = 384 * 256 + 256 * 128 + 129 * 128 + 256 + 32;   // 147872 > NN
    prep_all_kernel<<<(prep_n + 255) / 256, 256>>>(Wkq, Wv, att_w, Wf,
                                                   E_pos, E_deprel, E_deparc, edge_w);
    scatter_kernel<<<(EE + 255) / 256, 256>>>(edge_index);

    int mt = (NN + 127) / 128;   // 391
    {
        dim3 grid(384 / 64, mt);
        gemm1_kernel<<<grid, 256>>>(inp);
    }

    edge_kernel<<<(NN * 32 + 255) / 256, 256>>>(edge_index, relpos, deprel, deparc, edge_w, attn);

    {
        dim3 grid(256 / 64, mt);
        gemm2_kernel<<<grid, 256>>>(final_bias, out);
    }
}

// round 12
// speedup vs baseline: 2.5663x; 1.1905x over previous
#include <cuda_runtime.h>
#include <cuda_bf16.h>
#include <cstdint>

#define NN 50000
#define EE 500000
#define DD 256
#define HH 4
#define MAXDEG 96

// ------------------- device scratch (no allocations allowed) -------------------
// 128-col sections in NATURAL order: col = h*32 + k. float4 at lane*4 holds
// (h = lane>>3, k = (lane&7)*4 .. +3).
__device__ float g_WcatT[384 * 256];    // [n=384][k=256], tf32-rounded. rows: 0-127 v | 128-255 A_src | 256-383 A_tgt
__device__ float g_WfT[256 * 128];      // [n=256][k=128], tf32-rounded
__device__ float g_big[NN * 384];       // [N, 384] fp32
__device__ float g_Apos[129 * 128];     // [pos][h*32+k] fp32
__device__ float g_Bdr[64 * 4];         // [deprel][h]
__device__ float g_Bda[8 * 4];          // [deparc][h]
__device__ float g_agg[NN * 128];       // [n][h*32+dv], tf32-rounded (GEMM2 A operand)
__device__ int   g_cnt[NN];
__device__ int2  g_slot2[NN * MAXDEG];  // packed: w0 = src|relpos<<16|deprel<<23|deparc<<29, w1 = e

// ------------------- helpers -------------------
__device__ __forceinline__ unsigned f2tf(float x) {
    unsigned r;
    asm("cvt.rna.tf32.f32 %0, %1;" : "=r"(r) : "f"(x));
    return r;
}
__device__ __forceinline__ float f2tff(float x) { return __uint_as_float(f2tf(x)); }

__device__ __forceinline__ void cp_async16(void* smem, const void* gmem, bool pred) {
    unsigned sa = (unsigned)__cvta_generic_to_shared(smem);
    int sz = pred ? 16 : 0;
    asm volatile("cp.async.cg.shared.global [%0], [%1], 16, %2;" :: "r"(sa), "l"(gmem), "r"(sz));
}
__device__ __forceinline__ void cp_commit() { asm volatile("cp.async.commit_group;"); }
__device__ __forceinline__ void cp_wait0() { asm volatile("cp.async.wait_group 0;" ::: "memory"); }

__device__ __forceinline__ void mma_tf32(float* c, const unsigned* a, const unsigned* b) {
    asm volatile(
        "mma.sync.aligned.m16n8k8.row.col.f32.tf32.tf32.f32 "
        "{%0,%1,%2,%3}, {%4,%5,%6,%7}, {%8,%9}, {%0,%1,%2,%3};"
        : "+f"(c[0]), "+f"(c[1]), "+f"(c[2]), "+f"(c[3])
        : "r"(a[0]), "r"(a[1]), "r"(a[2]), "r"(a[3]), "r"(b[0]), "r"(b[1]));
}

// ------------------- merged prep kernel (zero cnt + weights + tables) -------------------
__global__ void prep_all_kernel(const float* __restrict__ Wkq,
                                const float* __restrict__ Wv,
                                const float* __restrict__ att_w,
                                const float* __restrict__ Wf,
                                const float* __restrict__ E_pos,
                                const float* __restrict__ E_deprel,
                                const float* __restrict__ E_deparc,
                                const float* __restrict__ edge_w) {
    int t = blockIdx.x * blockDim.x + threadIdx.x;
    if (t < NN) g_cnt[t] = 0;

    if (t < 384 * 256) {
        int c = t >> 8, d = t & 255;
        int sec = c >> 7;
        int m = c & 127;               // m = h*32 + k (natural)
        int h = m >> 5, k = m & 31;
        float o;
        if (sec == 0) {
            o = Wv[d * 128 + m];
        } else {
            int joff = (sec == 2) ? 32 : 0;
            float s = 0.f;
            #pragma unroll
            for (int j = 0; j < 32; j++)
                s += Wkq[d * 128 + h * 32 + j] * att_w[h * 3072 + (joff + j) * 32 + k];
            o = s;
        }
        g_WcatT[c * 256 + d] = f2tff(o);
        return;
    }
    int u = t - 384 * 256;
    if (u < 256 * 128) {
        int c = u & 127, n = u >> 7;
        g_WfT[n * 128 + c] = f2tff(Wf[c * 256 + n]);
        return;
    }
    u -= 256 * 128;
    if (u < 129 * 128) {
        int p = u >> 7, m = u & 127;
        int h = m >> 5, k = m & 31;
        float s = 0.f;
        #pragma unroll
        for (int j = 0; j < 32; j++)
            s += E_pos[p * 32 + j] * att_w[h * 3072 + (64 + j) * 32 + k];
        g_Apos[u] = s;
        return;
    }
    u -= 129 * 128;
    if (u < 256) {
        int r = u / 4, h = u % 4;
        float s = 0.f;
        #pragma unroll
        for (int j = 0; j < 32; j++)
            s += E_deprel[r * 32 + j] * edge_w[h * 96 + j];
        g_Bdr[u] = s;
        return;
    }
    u -= 256;
    if (u < 32) {
        int a = u / 4, h = u % 4;
        float s = 0.f;
        #pragma unroll
        for (int j = 0; j < 32; j++)
            s += E_deparc[a * 32 + j] * edge_w[h * 96 + 32 + j];
        g_Bda[u] = s;
    }
}

// ------------------- scatter: pack all per-edge scalars into the slot record -------------------
__global__ void scatter_kernel(const int* __restrict__ edge_index,
                               const int* __restrict__ relpos,
                               const int* __restrict__ deprel,
                               const int* __restrict__ deparc) {
    int e = blockIdx.x * blockDim.x + threadIdx.x;
    if (e >= EE) return;
    int t  = edge_index[EE + e];
    int s  = edge_index[e];
    int rp = relpos[e];          // 0..64 -> 7 bits
    int dr = deprel[e];          // 0..63 -> 6 bits
    int da = deparc[e];          // 0..7  -> 3 bits
    int w0 = s | (rp << 16) | (dr << 23) | (da << 29);
    int r = atomicAdd(&g_cnt[t], 1);
    if (r < MAXDEG) g_slot2[t * MAXDEG + r] = make_int2(w0, e);
}

// ------------------- tf32 mma.sync GEMM, cp.async double-buffered (round-3 proven) -------------------
template<bool ACVT>
__device__ __forceinline__ void gemm_body(int M, int K,
                                          const float* __restrict__ A, int lda,
                                          const float* __restrict__ BT, int ldbt,
                                          float* __restrict__ C, int ldc,
                                          const float* __restrict__ bias,
                                          float (*As)[128 * 32], float (*Bs)[64 * 32]) {
    int m0 = blockIdx.y * 128;
    int n0 = blockIdx.x * 64;
    int tid = threadIdx.x;
    int wid = tid >> 5, lane = tid & 31;
    int wm = (wid & 3) * 32;
    int wn = (wid >> 2) * 32;
    int r = lane >> 2, cq = lane & 3;

    float acc[2][4][4];
    #pragma unroll
    for (int i = 0; i < 2; i++)
        #pragma unroll
        for (int j = 0; j < 4; j++)
            #pragma unroll
            for (int q = 0; q < 4; q++) acc[i][j][q] = 0.f;

    auto stage = [&](int buf, int k0) {
        #pragma unroll
        for (int l = 0; l < 4; l++) {
            int idx = tid + l * 256;
            int row = idx >> 3, c = idx & 7;
            float* dst = As[buf] + row * 32 + ((c ^ (row & 7)) << 2);
            cp_async16(dst, A + (size_t)(m0 + row) * lda + k0 + c * 4, m0 + row < M);
        }
        #pragma unroll
        for (int l = 0; l < 2; l++) {
            int idx = tid + l * 256;
            int row = idx >> 3, c = idx & 7;
            float* dst = Bs[buf] + row * 32 + ((c ^ (row & 7)) << 2);
            cp_async16(dst, BT + (size_t)(n0 + row) * ldbt + k0 + c * 4, true);
        }
    };

    int T = K >> 5;
    stage(0, 0);
    cp_commit();

    for (int t = 0; t < T; t++) {
        cp_wait0();
        __syncthreads();
        if (t + 1 < T) { stage((t + 1) & 1, (t + 1) * 32); cp_commit(); }

        const float* Ab = As[t & 1];
        const float* Bb = Bs[t & 1];
        #pragma unroll
        for (int kf = 0; kf < 4; kf++) {
            int o0 = (((2 * kf) ^ r) << 2) + cq;
            int o1 = (((2 * kf + 1) ^ r) << 2) + cq;
            unsigned afr[2][4], bfr[4][2];
            #pragma unroll
            for (int mf = 0; mf < 2; mf++) {
                const float* b0 = Ab + (wm + mf * 16 + r) * 32;
                const float* b8 = b0 + 8 * 32;
                if (ACVT) {
                    afr[mf][0] = f2tf(b0[o0]); afr[mf][1] = f2tf(b8[o0]);
                    afr[mf][2] = f2tf(b0[o1]); afr[mf][3] = f2tf(b8[o1]);
                } else {
                    afr[mf][0] = __float_as_uint(b0[o0]); afr[mf][1] = __float_as_uint(b8[o0]);
                    afr[mf][2] = __float_as_uint(b0[o1]); afr[mf][3] = __float_as_uint(b8[o1]);
                }
            }
            #pragma unroll
            for (int nf = 0; nf < 4; nf++) {
                const float* bb = Bb + (wn + nf * 8 + r) * 32;
                bfr[nf][0] = __float_as_uint(bb[o0]);
                bfr[nf][1] = __float_as_uint(bb[o1]);
            }
            #pragma unroll
            for (int mf = 0; mf < 2; mf++)
                #pragma unroll
                for (int nf = 0; nf < 4; nf++)
                    mma_tf32(acc[mf][nf], afr[mf], bfr[nf]);
        }
        __syncthreads();
    }

    #pragma unroll
    for (int mf = 0; mf < 2; mf++) {
        #pragma unroll
        for (int nf = 0; nf < 4; nf++) {
            int col = n0 + wn + nf * 8 + cq * 2;
            float b0 = 0.f, b1 = 0.f;
            if (bias) { b0 = bias[col]; b1 = bias[col + 1]; }
            int row0 = m0 + wm + mf * 16 + r;
            if (row0 < M)
                *(float2*)(C + (size_t)row0 * ldc + col) =
                    make_float2(acc[mf][nf][0] + b0, acc[mf][nf][1] + b1);
            int row1 = row0 + 8;
            if (row1 < M)
                *(float2*)(C + (size_t)row1 * ldc + col) =
                    make_float2(acc[mf][nf][2] + b0, acc[mf][nf][3] + b1);
        }
    }
}

__global__ void gemm1_kernel(const float* __restrict__ inp) {
    __shared__ float As[2][128 * 32];
    __shared__ float Bs[2][64 * 32];
    gemm_body<true>(NN, 256, inp, 256, g_WcatT, 256, g_big, 384, nullptr, As, Bs);
}

__global__ void gemm2_kernel(const float* __restrict__ bias, float* __restrict__ out) {
    __shared__ float As[2][128 * 32];
    __shared__ float Bs[2][64 * 32];
    gemm_body<false>(NN, 128, g_agg, 128, g_WfT, 128, out, 256, bias, As, Bs);
}

// ------------------- edge/attention kernel: one warp per target node -------------------
// Natural [h*32+k] layout; ALL per-edge scalars come from the packed slot record
// (coalesced int2 load + shfl + bit-extract) -> zero scattered index loads.
// NOTE: every __shfl_sync is executed warp-uniformly (never inside a divergent branch).
__global__ void edge_kernel(const float* __restrict__ edge_w,
                            float* __restrict__ attn) {
    int warp = (blockIdx.x * blockDim.x + threadIdx.x) >> 5;
    int lane = threadIdx.x & 31;
    if (warp >= NN) return;
    int n = warp;
    int h = lane >> 3;
    int kb = (lane & 7) * 4;

    float4 at4 = *(const float4*)(g_big + (size_t)n * 384 + 256 + lane * 4);
    float ew0 = edge_w[h * 96 + 64 + kb + 0];
    float ew1 = edge_w[h * 96 + 64 + kb + 1];
    float ew2 = edge_w[h * 96 + 64 + kb + 2];
    float ew3 = edge_w[h * 96 + 64 + kb + 3];
    float den0 = 0.f, den1 = 0.f, den2 = 0.f, den3 = 0.f;
    float acc0 = 0.f, acc1 = 0.f, acc2 = 0.f, acc3 = 0.f;

    int d = g_cnt[n];
    if (d > MAXDEG) d = MAXDEG;
    const int2* sl = g_slot2 + (size_t)n * MAXDEG;
    int2 sa = sl[lane], sb = sl[lane + 32], sc = sl[lane + 64];
    auto get_w0 = [&](int i) {
        int v = (i < 32) ? sa.x : ((i < 64) ? sb.x : sc.x);
        return __shfl_sync(0xffffffffu, v, i & 31);
    };
    auto get_w1 = [&](int i) {
        int v = (i < 32) ? sa.y : ((i < 64) ? sb.y : sc.y);
        return __shfl_sync(0xffffffffu, v, i & 31);
    };

    // pass 1: denominators (per-lane, no reduction)
    for (int i = 0; i < d; i++) {
        int w0 = get_w0(i);
        int s = w0 & 0xFFFF;
        int p = ((w0 >> 16) & 0x7F) + 64;
        float4 as4 = *(const float4*)(g_big + (size_t)s * 384 + 128 + lane * 4);
        float4 ap4 = *(const float4*)(g_Apos + p * 128 + lane * 4);
        float x0 = as4.x + at4.x + ap4.x; x0 = (x0 >= 0.f) ? x0 : 0.2f * x0;
        float x1 = as4.y + at4.y + ap4.y; x1 = (x1 >= 0.f) ? x1 : 0.2f * x1;
        float x2 = as4.z + at4.z + ap4.z; x2 = (x2 >= 0.f) ? x2 : 0.2f * x2;
        float x3 = as4.w + at4.w + ap4.w; x3 = (x3 >= 0.f) ? x3 : 0.2f * x3;
        den0 += __expf(x0); den1 += __expf(x1);
        den2 += __expf(x2); den3 += __expf(x3);
    }

    // fold 1/(den+eps) into beta weights (per-lane)
    ew0 = ew0 / (den0 + 1e-12f);
    ew1 = ew1 / (den1 + 1e-12f);
    ew2 = ew2 / (den2 + 1e-12f);
    ew3 = ew3 / (den3 + 1e-12f);

    // pass 2: recompute exp, 8-lane reduction, attn, v accumulation
    for (int i = 0; i < d; i++) {
        int w0 = get_w0(i);
        int e  = get_w1(i);          // warp-uniform shfl, BEFORE any divergence
        int s  = w0 & 0xFFFF;
        int p  = ((w0 >> 16) & 0x7F) + 64;
        int dr = (w0 >> 23) & 0x3F;
        int da = ((unsigned)w0 >> 29) & 0x7;
        float4 as4 = *(const float4*)(g_big + (size_t)s * 384 + 128 + lane * 4);
        float4 ap4 = *(const float4*)(g_Apos + p * 128 + lane * 4);
        float4 vv4 = *(const float4*)(g_big + (size_t)s * 384 + lane * 4);
        float bdr = g_Bdr[dr * 4 + h];
        float bda = g_Bda[da * 4 + h];
        float x0 = as4.x + at4.x + ap4.x; x0 = (x0 >= 0.f) ? x0 : 0.2f * x0;
        float x1 = as4.y + at4.y + ap4.y; x1 = (x1 >= 0.f) ? x1 : 0.2f * x1;
        float x2 = as4.z + at4.z + ap4.z; x2 = (x2 >= 0.f) ? x2 : 0.2f * x2;
        float x3 = as4.w + at4.w + ap4.w; x3 = (x3 >= 0.f) ? x3 : 0.2f * x3;
        float pl = __expf(x0) * ew0 + __expf(x1) * ew1
                 + __expf(x2) * ew2 + __expf(x3) * ew3;
        pl += __shfl_xor_sync(0xffffffffu, pl, 1);
        pl += __shfl_xor_sync(0xffffffffu, pl, 2);
        pl += __shfl_xor_sync(0xffffffffu, pl, 4);
        float y = bdr + bda + pl;
        float es = (y >= 0.f) ? y : 0.2f * y;
        acc0 += vv4.x * es;
        acc1 += vv4.y * es;
        acc2 += vv4.z * es;
        acc3 += vv4.w * es;
        if ((lane & 7) == 0)
            attn[(size_t)e * 4 + h] = es;     // lanes 0/8/16/24 -> one 16B txn
    }

    float4 o = make_float4(f2tff(acc0), f2tff(acc1), f2tff(acc2), f2tff(acc3));
    *(float4*)(g_agg + (size_t)n * 128 + lane * 4) = o;
}

// ------------------- launch -------------------
extern "C" void kernel_launch(void* const* d_in, const int* in_sizes, int n_in,
                              void* d_out, int out_size) {
    const float* inp        = (const float*)d_in[0];
    const int*   relpos     = (const int*)d_in[1];
    // d_in[2] word_rel_pos_edge: unused
    // d_in[3] deprel_ext_edge: unused
    const int*   edge_index = (const int*)d_in[4];
    const int*   deprel     = (const int*)d_in[5];
    const int*   deparc     = (const int*)d_in[6];
    const float* Wkq        = (const float*)d_in[7];
    const float* Wv         = (const float*)d_in[8];
    const float* att_w      = (const float*)d_in[9];
    const float* edge_w     = (const float*)d_in[10];
    const float* Wf         = (const float*)d_in[11];
    const float* final_bias = (const float*)d_in[12];
    const float* E_deprel   = (const float*)d_in[13];
    const float* E_deparc   = (const float*)d_in[14];
    const float* E_pos      = (const float*)d_in[15];

    float* out  = (float*)d_out;             // [N, 256]
    float* attn = out + (size_t)NN * DD;     // [E, 4]

    int prep_n = 384 * 256 + 256 * 128 + 129 * 128 + 256 + 32;   // 147872 > NN
    prep_all_kernel<<<(prep_n + 255) / 256, 256>>>(Wkq, Wv, att_w, Wf,
                                                   E_pos, E_deprel, E_deparc, edge_w);
    scatter_kernel<<<(EE + 255) / 256, 256>>>(edge_index, relpos, deprel, deparc);

    int mt = (NN + 127) / 128;   // 391
    {
        dim3 grid(384 / 64, mt);
        gemm1_kernel<<<grid, 256>>>(inp);
    }

    edge_kernel<<<(NN * 32 + 255) / 256, 256>>>(edge_w, attn);

    {
        dim3 grid(256 / 64, mt);
        gemm2_kernel<<<grid, 256>>>(final_bias, out);
    }
}